// round 2
// baseline (speedup 1.0000x reference)
#include <cuda_runtime.h>
#include <math.h>
#include <stdint.h>

// ---------------------------------------------------------------------------
// MixtureOfRecursionsEncoder: B=8, L=1024, D=1024, H=16, HD=64, DF=4096, MD=6
// Round 1: full fp32 (rel_err floor ~1e-6), GEMMs via packed fma.rn.f32x2.
// ---------------------------------------------------------------------------

#define BB   8
#define LL   1024
#define DD   1024
#define HH   16
#define HDD  64
#define DFF  4096
#define MDD  6
#define ROWS (BB * LL)            // 8192
#define NCUR (ROWS * DD)          // 8388608

typedef unsigned long long u64t;

// ---------------- device scratch (static allocation; no cudaMalloc) --------
__device__ float g_cur[ROWS * DD];
__device__ float g_ln[ROWS * DD];
__device__ float g_qkv[ROWS * 3 * DD];
__device__ float g_scores[(size_t)BB * HH * LL * LL];   // 536 MB
__device__ float g_ctx[ROWS * DD];
__device__ float g_x2[ROWS * DD];
__device__ float g_hid[(size_t)ROWS * DFF];
__device__ float g_logits[ROWS * MDD];
__device__ int   g_depths[ROWS];

// ---------------- small helpers --------------------------------------------
__device__ __forceinline__ float gelu_erf(float x) {
    return 0.5f * x * (1.0f + erff(x * 0.70710678118654752440f));
}

__device__ __forceinline__ u64t dup2(float v) {
    u64t r;
    asm("mov.b64 %0, {%1, %1};" : "=l"(r) : "r"(__float_as_uint(v)));
    return r;
}
__device__ __forceinline__ void fma2(u64t& acc, u64t a, u64t b) {
    asm("fma.rn.f32x2 %0, %1, %2, %0;" : "+l"(acc) : "l"(a), "l"(b));
}
__device__ __forceinline__ float2 unpack2(u64t v) {
    unsigned lo, hi;
    asm("mov.b64 {%0, %1}, %2;" : "=r"(lo), "=r"(hi) : "l"(v));
    return make_float2(__uint_as_float(lo), __uint_as_float(hi));
}

__device__ __forceinline__ float warp_sum(float v) {
    #pragma unroll
    for (int o = 16; o > 0; o >>= 1) v += __shfl_xor_sync(0xffffffffu, v, o);
    return v;
}
__device__ __forceinline__ float warp_max(float v) {
    #pragma unroll
    for (int o = 16; o > 0; o >>= 1) v = fmaxf(v, __shfl_xor_sync(0xffffffffu, v, o));
    return v;
}

// ---------------- 128x128x16 NT GEMM core (C[m,n] = sum_k A[m,k]*W[n,k]) ---
// 256 threads, each computes 8(m) x 8(n) held as 8 x 4 packed f32x2 pairs.
__device__ __forceinline__ void gemm128_core(
    const float* __restrict__ A, int lda,
    const float* __restrict__ W, int ldw,
    int K, int m0, int n0,
    float (&As)[16][132], float (&Bs)[16][132],
    u64t (&acc)[8][4])
{
    const int tid = threadIdx.x;
    const int tm  = (tid >> 4) << 3;   // 0..120
    const int tn  = (tid & 15) << 3;   // 0..120

    for (int k0 = 0; k0 < K; k0 += 16) {
        #pragma unroll
        for (int t = 0; t < 2; t++) {
            int idx = tid + t * 256;
            int row = idx >> 2;
            int kc  = (idx & 3) << 2;
            float4 va = *(const float4*)(A + (size_t)(m0 + row) * lda + (k0 + kc));
            As[kc + 0][row] = va.x; As[kc + 1][row] = va.y;
            As[kc + 2][row] = va.z; As[kc + 3][row] = va.w;
            float4 vb = *(const float4*)(W + (size_t)(n0 + row) * ldw + (k0 + kc));
            Bs[kc + 0][row] = vb.x; Bs[kc + 1][row] = vb.y;
            Bs[kc + 2][row] = vb.z; Bs[kc + 3][row] = vb.w;
        }
        __syncthreads();
        #pragma unroll
        for (int k = 0; k < 16; k++) {
            float4 a0 = *(const float4*)&As[k][tm];
            float4 a1 = *(const float4*)&As[k][tm + 4];
            u64t b0 = *(const u64t*)&Bs[k][tn];
            u64t b1 = *(const u64t*)&Bs[k][tn + 2];
            u64t b2 = *(const u64t*)&Bs[k][tn + 4];
            u64t b3 = *(const u64t*)&Bs[k][tn + 6];
            float av[8] = {a0.x, a0.y, a0.z, a0.w, a1.x, a1.y, a1.z, a1.w};
            #pragma unroll
            for (int i = 0; i < 8; i++) {
                u64t ad = dup2(av[i]);
                fma2(acc[i][0], ad, b0);
                fma2(acc[i][1], ad, b1);
                fma2(acc[i][2], ad, b2);
                fma2(acc[i][3], ad, b3);
            }
        }
        __syncthreads();
    }
}

// EPI: 0=store, 1=+bias, 2=+bias,gelu, 3=+bias,+res, 4=+bias,+res,depth-mask
template<int EPI>
__global__ void __launch_bounds__(256, 2)
gemm_nt_kernel(const float* __restrict__ A, int lda,
               const float* __restrict__ W, int ldw,
               const float* __restrict__ bias,
               const float* __restrict__ res,
               const int* __restrict__ depths, int level,
               float* __restrict__ C, int ldc, int K)
{
    __shared__ float As[16][132];
    __shared__ float Bs[16][132];
    u64t acc[8][4];
    #pragma unroll
    for (int i = 0; i < 8; i++)
        #pragma unroll
        for (int j = 0; j < 4; j++) acc[i][j] = 0ull;

    const int m0 = blockIdx.y << 7;
    const int n0 = blockIdx.x << 7;
    gemm128_core(A, lda, W, ldw, K, m0, n0, As, Bs, acc);

    const int tid = threadIdx.x;
    const int tm  = (tid >> 4) << 3;
    const int tn  = (tid & 15) << 3;
    #pragma unroll
    for (int i = 0; i < 8; i++) {
        int m = m0 + tm + i;
        if (EPI == 4) { if (depths[m] < level) continue; }
        #pragma unroll
        for (int j = 0; j < 4; j++) {
            float2 r = unpack2(acc[i][j]);
            int n = n0 + tn + 2 * j;
            if (EPI >= 1) { r.x += bias[n]; r.y += bias[n + 1]; }
            if (EPI == 2) { r.x = gelu_erf(r.x); r.y = gelu_erf(r.y); }
            if (EPI == 3 || EPI == 4) {
                r.x += res[(size_t)m * ldc + n];
                r.y += res[(size_t)m * ldc + n + 1];
            }
            *(float2*)&C[(size_t)m * ldc + n] = r;
        }
    }
}

// ---------------- attention scores: S = Q @ K^T per (b,h) ------------------
__global__ void __launch_bounds__(256, 2)
attn_scores_kernel(const float* __restrict__ qkv, float* __restrict__ scores)
{
    __shared__ float As[16][132];
    __shared__ float Bs[16][132];
    u64t acc[8][4];
    #pragma unroll
    for (int i = 0; i < 8; i++)
        #pragma unroll
        for (int j = 0; j < 4; j++) acc[i][j] = 0ull;

    const int z = blockIdx.z;          // b*16 + h
    const int b = z >> 4, h = z & 15;
    const float* Q  = qkv + (size_t)b * LL * (3 * DD) + h * HDD;
    const float* Kp = Q + DD;
    const int m0 = blockIdx.y << 7;
    const int n0 = blockIdx.x << 7;
    gemm128_core(Q, 3 * DD, Kp, 3 * DD, HDD, m0, n0, As, Bs, acc);

    float* C = scores + (size_t)z * LL * LL;
    const int tid = threadIdx.x;
    const int tm  = (tid >> 4) << 3;
    const int tn  = (tid & 15) << 3;
    #pragma unroll
    for (int i = 0; i < 8; i++) {
        int m = m0 + tm + i;
        #pragma unroll
        for (int j = 0; j < 4; j++) {
            float2 r = unpack2(acc[i][j]);
            *(float2*)&C[(size_t)m * LL + n0 + tn + 2 * j] = r;
        }
    }
}

// ---------------- softmax over rows of scores (scale 1/8 applied here) -----
__global__ void softmax_kernel(float* __restrict__ scores)
{
    size_t row = blockIdx.x;
    float4* p = (float4*)(scores + row * LL);
    float4 v = p[threadIdx.x];
    v.x *= 0.125f; v.y *= 0.125f; v.z *= 0.125f; v.w *= 0.125f;

    __shared__ float sh[8];
    float mx = fmaxf(fmaxf(v.x, v.y), fmaxf(v.z, v.w));
    mx = warp_max(mx);
    int wid = threadIdx.x >> 5, lane = threadIdx.x & 31;
    if (lane == 0) sh[wid] = mx;
    __syncthreads();
    if (wid == 0) {
        float m = (lane < 8) ? sh[lane] : -1e30f;
        m = warp_max(m);
        if (lane == 0) sh[0] = m;
    }
    __syncthreads();
    float m = sh[0];
    __syncthreads();

    v.x = __expf(v.x - m); v.y = __expf(v.y - m);
    v.z = __expf(v.z - m); v.w = __expf(v.w - m);
    float s = v.x + v.y + v.z + v.w;
    s = warp_sum(s);
    if (lane == 0) sh[wid] = s;
    __syncthreads();
    if (wid == 0) {
        float t = (lane < 8) ? sh[lane] : 0.f;
        t = warp_sum(t);
        if (lane == 0) sh[0] = t;
    }
    __syncthreads();
    float inv = 1.0f / sh[0];
    v.x *= inv; v.y *= inv; v.z *= inv; v.w *= inv;
    p[threadIdx.x] = v;
}

// ---------------- ctx = P @ V per (b,h): 1024 x 64 x 1024, NN GEMM ---------
__global__ void __launch_bounds__(256, 2)
attn_ctx_kernel(const float* __restrict__ scores, const float* __restrict__ qkv,
                float* __restrict__ ctx)
{
    __shared__ float As[16][132];
    __shared__ float Bs[16][68];
    const int z = blockIdx.z, b = z >> 4, h = z & 15;
    const float* P = scores + (size_t)z * LL * LL;                         // lda LL
    const float* V = qkv + (size_t)b * LL * (3 * DD) + 2 * DD + h * HDD;   // ldb 3D
    float* C = ctx + (size_t)b * LL * DD + h * HDD;                        // ldc DD

    const int m0 = blockIdx.y << 7;
    const int tid = threadIdx.x;
    const int tm = (tid >> 4) << 3;    // 0..120 (m)
    const int tn = (tid & 15) << 2;    // 0..60  (n)
    u64t acc[8][2];
    #pragma unroll
    for (int i = 0; i < 8; i++) { acc[i][0] = 0ull; acc[i][1] = 0ull; }

    for (int k0 = 0; k0 < LL; k0 += 16) {
        #pragma unroll
        for (int t = 0; t < 2; t++) {
            int idx = tid + t * 256;
            int row = idx >> 2;
            int kc  = (idx & 3) << 2;
            float4 va = *(const float4*)(P + (size_t)(m0 + row) * LL + k0 + kc);
            As[kc + 0][row] = va.x; As[kc + 1][row] = va.y;
            As[kc + 2][row] = va.z; As[kc + 3][row] = va.w;
        }
        {
            int row = tid >> 4;
            int col = (tid & 15) << 2;
            float4 vb = *(const float4*)(V + (size_t)(k0 + row) * (3 * DD) + col);
            Bs[row][col + 0] = vb.x; Bs[row][col + 1] = vb.y;
            Bs[row][col + 2] = vb.z; Bs[row][col + 3] = vb.w;
        }
        __syncthreads();
        #pragma unroll
        for (int k = 0; k < 16; k++) {
            float4 a0 = *(const float4*)&As[k][tm];
            float4 a1 = *(const float4*)&As[k][tm + 4];
            u64t b0 = *(const u64t*)&Bs[k][tn];
            u64t b1 = *(const u64t*)&Bs[k][tn + 2];
            float av[8] = {a0.x, a0.y, a0.z, a0.w, a1.x, a1.y, a1.z, a1.w};
            #pragma unroll
            for (int i = 0; i < 8; i++) {
                u64t ad = dup2(av[i]);
                fma2(acc[i][0], ad, b0);
                fma2(acc[i][1], ad, b1);
            }
        }
        __syncthreads();
    }
    #pragma unroll
    for (int i = 0; i < 8; i++) {
        int m = m0 + tm + i;
        #pragma unroll
        for (int j = 0; j < 2; j++) {
            float2 r = unpack2(acc[i][j]);
            *(float2*)&C[(size_t)m * DD + tn + 2 * j] = r;
        }
    }
}

// ---------------- LayerNorm over last dim (D=1024), one block per row ------
__global__ void ln_kernel(const float* __restrict__ in, const float* __restrict__ w,
                          const float* __restrict__ b, float* __restrict__ out)
{
    const int row = blockIdx.x;
    const float4* x4 = (const float4*)(in + (size_t)row * DD);
    float4 v = x4[threadIdx.x];                  // 256 threads * 4 = 1024
    float s  = v.x + v.y + v.z + v.w;
    float s2 = v.x * v.x + v.y * v.y + v.z * v.z + v.w * v.w;

    __shared__ float shs[8], shq[8];
    s  = warp_sum(s);
    s2 = warp_sum(s2);
    int wid = threadIdx.x >> 5, lane = threadIdx.x & 31;
    if (lane == 0) { shs[wid] = s; shq[wid] = s2; }
    __syncthreads();
    if (wid == 0) {
        float a = (lane < 8) ? shs[lane] : 0.f;
        float c = (lane < 8) ? shq[lane] : 0.f;
        a = warp_sum(a); c = warp_sum(c);
        if (lane == 0) {
            float mu = a * (1.0f / DD);
            float var = c * (1.0f / DD) - mu * mu;
            shs[0] = mu;
            shq[0] = rsqrtf(var + 1e-5f);
        }
    }
    __syncthreads();
    float mu = shs[0], rstd = shq[0];
    float4 wv = ((const float4*)w)[threadIdx.x];
    float4 bv = ((const float4*)b)[threadIdx.x];
    float4 o;
    o.x = (v.x - mu) * rstd * wv.x + bv.x;
    o.y = (v.y - mu) * rstd * wv.y + bv.y;
    o.z = (v.z - mu) * rstd * wv.z + bv.z;
    o.w = (v.w - mu) * rstd * wv.w + bv.w;
    ((float4*)(out + (size_t)row * DD))[threadIdx.x] = o;
}

// ---------------- router: logits (N=6 dot products) + argmax depth ---------
__global__ void router_kernel(const float* __restrict__ rh,
                              const float* __restrict__ w2,
                              const float* __restrict__ b2,
                              float* __restrict__ logits, int* __restrict__ depths)
{
    const int row = blockIdx.x;
    const int tid = threadIdx.x;   // 128 threads
    float part[MDD] = {0, 0, 0, 0, 0, 0};
    const float* x = rh + (size_t)row * DD;
    for (int i = tid; i < DD; i += 128) {
        float v = x[i];
        #pragma unroll
        for (int d = 0; d < MDD; d++) part[d] = fmaf(v, w2[d * DD + i], part[d]);
    }
    #pragma unroll
    for (int d = 0; d < MDD; d++) part[d] = warp_sum(part[d]);

    __shared__ float sh[MDD][4];
    int wid = tid >> 5, lane = tid & 31;
    if (lane == 0) {
        #pragma unroll
        for (int d = 0; d < MDD; d++) sh[d][wid] = part[d];
    }
    __syncthreads();
    if (tid == 0) {
        float best = -1e30f;
        int bi = 0;
        #pragma unroll
        for (int d = 0; d < MDD; d++) {
            float Lg = sh[d][0] + sh[d][1] + sh[d][2] + sh[d][3] + b2[d];
            logits[(size_t)row * MDD + d] = Lg;
            if (Lg > best) { best = Lg; bi = d; }
        }
        depths[row] = bi + 1;
    }
}

// ---------------- utility: copy & output packing ---------------------------
__global__ void copy_kernel(const float* __restrict__ in, float* __restrict__ out)
{
    size_t i = (size_t)blockIdx.x * blockDim.x + threadIdx.x;
    ((float4*)out)[i] = ((const float4*)in)[i];
}

__global__ void pack_kernel(const float* __restrict__ cur, const int* __restrict__ depths,
                            const float* __restrict__ logits, float* __restrict__ out,
                            int out_size)
{
    int i = blockIdx.x * blockDim.x + threadIdx.x;
    if (i >= out_size) return;
    if (i < NCUR) {
        out[i] = cur[i];
    } else {
        int r = i - NCUR;
        if (r < ROWS)                     out[i] = (float)depths[r];
        else if (r - ROWS < ROWS * MDD)   out[i] = logits[r - ROWS];
        else                              out[i] = 0.0f;
    }
}

// ---------------------------------------------------------------------------
extern "C" void kernel_launch(void* const* d_in, const int* in_sizes, int n_in,
                              void* d_out, int out_size)
{
    (void)in_sizes; (void)n_in;
    const float* x           = (const float*)d_in[0];
    const float* attn_norm_w = (const float*)d_in[1];
    const float* attn_norm_b = (const float*)d_in[2];
    const float* in_proj_w   = (const float*)d_in[3];
    const float* in_proj_b   = (const float*)d_in[4];
    const float* out_proj_w  = (const float*)d_in[5];
    const float* out_proj_b  = (const float*)d_in[6];
    const float* ffn_norm_w  = (const float*)d_in[7];
    const float* ffn_norm_b  = (const float*)d_in[8];
    const float* ffn_w1      = (const float*)d_in[9];
    const float* ffn_b1      = (const float*)d_in[10];
    const float* ffn_w2      = (const float*)d_in[11];
    const float* ffn_b2      = (const float*)d_in[12];
    const float* rt_norm_w   = (const float*)d_in[13];
    const float* rt_norm_b   = (const float*)d_in[14];
    const float* rt_w1       = (const float*)d_in[15];
    const float* rt_b1       = (const float*)d_in[16];
    const float* rt_w2       = (const float*)d_in[17];
    const float* rt_b2       = (const float*)d_in[18];

    float *cur, *ln, *qkv, *scores, *ctx, *x2, *hid, *logits;
    int* depths;
    cudaGetSymbolAddress((void**)&cur,    g_cur);
    cudaGetSymbolAddress((void**)&ln,     g_ln);
    cudaGetSymbolAddress((void**)&qkv,    g_qkv);
    cudaGetSymbolAddress((void**)&scores, g_scores);
    cudaGetSymbolAddress((void**)&ctx,    g_ctx);
    cudaGetSymbolAddress((void**)&x2,     g_x2);
    cudaGetSymbolAddress((void**)&hid,    g_hid);
    cudaGetSymbolAddress((void**)&logits, g_logits);
    cudaGetSymbolAddress((void**)&depths, g_depths);

    // cur = x
    copy_kernel<<<NCUR / (256 * 4), 256>>>(x, cur);

    // ---- router: depths = argmax(logits) + 1 ----
    ln_kernel<<<ROWS, 256>>>(x, rt_norm_w, rt_norm_b, ln);
    gemm_nt_kernel<2><<<dim3(DD / 128, ROWS / 128), 256>>>(
        ln, DD, rt_w1, DD, rt_b1, nullptr, nullptr, 0, ctx, DD, DD);
    router_kernel<<<ROWS, 128>>>(ctx, rt_w2, rt_b2, logits, depths);

    // ---- 6 recursion levels ----
    for (int level = 1; level <= MDD; level++) {
        // pre-norm attention
        ln_kernel<<<ROWS, 256>>>(cur, attn_norm_w, attn_norm_b, ln);
        gemm_nt_kernel<1><<<dim3(3 * DD / 128, ROWS / 128), 256>>>(
            ln, DD, in_proj_w, DD, in_proj_b, nullptr, nullptr, 0, qkv, 3 * DD, DD);
        attn_scores_kernel<<<dim3(LL / 128, LL / 128, BB * HH), 256>>>(qkv, scores);
        softmax_kernel<<<BB * HH * LL, 256>>>(scores);
        attn_ctx_kernel<<<dim3(1, LL / 128, BB * HH), 256>>>(scores, qkv, ctx);
        // x2 = cur + ctx @ Wo^T + bo
        gemm_nt_kernel<3><<<dim3(DD / 128, ROWS / 128), 256>>>(
            ctx, DD, out_proj_w, DD, out_proj_b, cur, nullptr, 0, x2, DD, DD);
        // pre-norm FFN
        ln_kernel<<<ROWS, 256>>>(x2, ffn_norm_w, ffn_norm_b, ln);
        gemm_nt_kernel<2><<<dim3(DFF / 128, ROWS / 128), 256>>>(
            ln, DD, ffn_w1, DD, ffn_b1, nullptr, nullptr, 0, hid, DFF, DD);
        // cur = (depth >= level) ? x2 + hid @ W2^T + b2 : cur
        gemm_nt_kernel<4><<<dim3(DD / 128, ROWS / 128), 256>>>(
            hid, DFF, ffn_w2, DFF, ffn_b2, x2, depths, level, cur, DD, DFF);
    }

    // ---- pack outputs: cur, depths (as float), logits ----
    int nblk = (out_size + 255) / 256;
    pack_kernel<<<nblk, 256>>>(cur, depths, logits, (float*)d_out, out_size);
}

// round 5
// speedup vs baseline: 2.3556x; 2.3556x over previous
#include <cuda_runtime.h>
#include <cuda_bf16.h>
#include <math.h>
#include <stdint.h>

#define BB   8
#define LL   1024
#define DD   1024
#define DFF  4096
#define MDD  6
#define ROWS (BB * LL)
#define NCUR (ROWS * DD)

__device__ float g_cur[ROWS * DD];
__device__ float g_ln[ROWS * DD];
__device__ float g_qkv[ROWS * 3 * DD];
__device__ float g_scores[(size_t)BB * 16 * LL * LL];
__device__ float g_ctx[ROWS * DD];
__device__ float g_x2[ROWS * DD];
__device__ float g_hid[(size_t)ROWS * DFF];
__device__ float g_logits[ROWS * MDD];
__device__ int   g_depths[ROWS];

// ---------------- helpers ----------------
__device__ __forceinline__ uint32_t smem_u32(const void* p) {
    uint32_t a;
    asm("{ .reg .u64 t; cvta.to.shared.u64 t, %1; cvt.u32.u64 %0, t; }" : "=r"(a) : "l"(p));
    return a;
}
__device__ __forceinline__ void ldmx4(uint32_t addr, uint32_t* r) {
    asm volatile("ldmatrix.sync.aligned.m8n8.x4.shared.b16 {%0,%1,%2,%3}, [%4];"
        : "=r"(r[0]), "=r"(r[1]), "=r"(r[2]), "=r"(r[3]) : "r"(addr));
}
__device__ __forceinline__ void ldmx2(uint32_t addr, uint32_t* r) {
    asm volatile("ldmatrix.sync.aligned.m8n8.x2.shared.b16 {%0,%1}, [%2];"
        : "=r"(r[0]), "=r"(r[1]) : "r"(addr));
}
__device__ __forceinline__ void mma_bf16(float* c, const uint32_t* a, const uint32_t* b) {
    asm volatile("mma.sync.aligned.m16n8k16.row.col.f32.bf16.bf16.f32 "
        "{%0,%1,%2,%3}, {%4,%5,%6,%7}, {%8,%9}, {%0,%1,%2,%3};"
        : "+f"(c[0]), "+f"(c[1]), "+f"(c[2]), "+f"(c[3])
        : "r"(a[0]), "r"(a[1]), "r"(a[2]), "r"(a[3]), "r"(b[0]), "r"(b[1]));
}
// fp32 float4 -> bf16 hi/lo pairs, padded-row store (8 bytes each)
__device__ __forceinline__ void split4(char* hi, char* lo, int off, float4 v) {
    __nv_bfloat162 h0 = __floats2bfloat162_rn(v.x, v.y);
    __nv_bfloat162 h1 = __floats2bfloat162_rn(v.z, v.w);
    float2 f0 = __bfloat1622float2(h0), f1 = __bfloat1622float2(h1);
    __nv_bfloat162 l0 = __floats2bfloat162_rn(v.x - f0.x, v.y - f0.y);
    __nv_bfloat162 l1 = __floats2bfloat162_rn(v.z - f1.x, v.w - f1.y);
    uint2 hv, lv;
    hv.x = *(uint32_t*)&h0; hv.y = *(uint32_t*)&h1;
    lv.x = *(uint32_t*)&l0; lv.y = *(uint32_t*)&l1;
    *(uint2*)(hi + off) = hv; *(uint2*)(lo + off) = lv;
}
__device__ __forceinline__ void split1(char* hi, char* lo, int off, float v) {
    __nv_bfloat16 h = __float2bfloat16_rn(v);
    __nv_bfloat16 l = __float2bfloat16_rn(v - __bfloat162float(h));
    *(unsigned short*)(hi + off) = *(unsigned short*)&h;
    *(unsigned short*)(lo + off) = *(unsigned short*)&l;
}
__device__ __forceinline__ float gelu_erf(float x) {
    return 0.5f * x * (1.0f + erff(x * 0.70710678118654752440f));
}
__device__ __forceinline__ float warp_sum(float v) {
    #pragma unroll
    for (int o = 16; o > 0; o >>= 1) v += __shfl_xor_sync(0xffffffffu, v, o);
    return v;
}
__device__ __forceinline__ float warp_max(float v) {
    #pragma unroll
    for (int o = 16; o > 0; o >>= 1) v = fmaxf(v, __shfl_xor_sync(0xffffffffu, v, o));
    return v;
}

// ---------------------------------------------------------------------------
// Split-bf16 NT GEMM on mma.sync: C = epi(A[M,K] @ W[N,K]^T)
// CTA 128 x NTILE, 8 warps (2m x 4n), warp tile 64 x (NTILE/4).
// K-chunk = 32. SMEM per stage: Ah[128][40]bf16, Al, Wh[NTILE][40], Wl.
// Row pad 40 elems (80B): conflict-free ldmatrix. 2 stages, reg-staged loads.
// Batched via blockIdx.z: base += (z>>hsh)*sz + (z&hmk)*sh per tensor.
// WTRANS: W[n,k] = Wbase[k*ldw + n]. EPI: 0 store, 1 +bias, 2 +bias+gelu,
// 3 +bias+res, 4 +bias+res+depth-mask.
// ---------------------------------------------------------------------------
template<int NTILE, int WTRANS>
__device__ __forceinline__ void load_regs(const float* Az, int lda, const float* Wz, int ldw,
                                          int n0, int c, int tid, float4* ra, float4* rw)
{
    const float* Ab = Az + (c << 5);
    #pragma unroll
    for (int i = 0; i < 4; i++) {
        int f = tid + (i << 8), r = f >> 3, g = f & 7;
        ra[i] = *(const float4*)(Ab + (size_t)r * lda + (g << 2));
    }
    if (WTRANS) {
        const float* Wb = Wz + (size_t)(c << 5) * ldw + n0;
        #pragma unroll
        for (int i = 0; i < NTILE / 32; i++) {
            int f = tid + (i << 8), k = f & 31, n4 = f >> 5;
            rw[i] = *(const float4*)(Wb + (size_t)k * ldw + (n4 << 2));
        }
    } else {
        const float* Wb = Wz + (size_t)n0 * ldw + (c << 5);
        #pragma unroll
        for (int i = 0; i < NTILE / 32; i++) {
            int f = tid + (i << 8), r = f >> 3, g = f & 7;
            rw[i] = *(const float4*)(Wb + (size_t)r * ldw + (g << 2));
        }
    }
}

template<int NTILE, int WTRANS>
__device__ __forceinline__ void store_regs(char* stg, int tid, const float4* ra, const float4* rw)
{
    char* Ah = stg;
    char* Al = stg + 10240;
    char* Wh = stg + 20480;
    char* Wl = Wh + NTILE * 80;
    #pragma unroll
    for (int i = 0; i < 4; i++) {
        int f = tid + (i << 8), r = f >> 3, g = f & 7;
        split4(Ah, Al, r * 80 + g * 8, ra[i]);
    }
    if (WTRANS) {
        #pragma unroll
        for (int i = 0; i < NTILE / 32; i++) {
            int f = tid + (i << 8), k = f & 31, n = (f >> 5) << 2;
            split1(Wh, Wl, (n + 0) * 80 + k * 2, rw[i].x);
            split1(Wh, Wl, (n + 1) * 80 + k * 2, rw[i].y);
            split1(Wh, Wl, (n + 2) * 80 + k * 2, rw[i].z);
            split1(Wh, Wl, (n + 3) * 80 + k * 2, rw[i].w);
        }
    } else {
        #pragma unroll
        for (int i = 0; i < NTILE / 32; i++) {
            int f = tid + (i << 8), r = f >> 3, g = f & 7;
            split4(Wh, Wl, r * 80 + g * 8, rw[i]);
        }
    }
}

template<int NT>
__device__ __forceinline__ void compute_chunk(uint32_t stg, int warp_m, int warp_n,
                                              int lane, float* acc)
{
    const uint32_t aAh = stg + (warp_m * 64 + (lane & 15)) * 80 + ((lane >> 4) & 1) * 16;
    const uint32_t aB  = stg + 20480 + (warp_n * NT * 8 + (lane & 7)) * 80 + ((lane >> 3) & 1) * 16;
    #pragma unroll
    for (int ks = 0; ks < 2; ks++) {
        const uint32_t kso = ks * 32;
        uint32_t bh[NT][2], bl[NT][2];
        #pragma unroll
        for (int nt = 0; nt < NT; nt++) {
            ldmx2(aB + nt * 640 + kso, bh[nt]);
            ldmx2(aB + NT * 2560 + nt * 640 + kso, bl[nt]);
        }
        #pragma unroll
        for (int mt = 0; mt < 4; mt++) {
            uint32_t ah[4], al[4];
            ldmx4(aAh + mt * 1280 + kso, ah);
            ldmx4(aAh + 10240 + mt * 1280 + kso, al);
            #pragma unroll
            for (int nt = 0; nt < NT; nt++) {
                float* c = acc + (mt * NT + nt) * 4;
                mma_bf16(c, ah, bh[nt]);
                mma_bf16(c, ah, bl[nt]);
                mma_bf16(c, al, bh[nt]);
            }
        }
    }
}

template<int EPI, int NTILE, int WTRANS>
__global__ void __launch_bounds__(256)
gemm_mma(const float* __restrict__ A, int lda, long saz, long sah,
         const float* __restrict__ W, int ldw, long swz, long swh,
         const float* __restrict__ bias, const float* __restrict__ res,
         const int* __restrict__ depths, int level,
         float* __restrict__ C, int ldc, long scz, long sch,
         int hsh, int hmk, int K)
{
    extern __shared__ __align__(16) char smem[];
    constexpr int NT  = NTILE / 32;
    constexpr int STG = 20480 + 2 * NTILE * 80;
    const int tid = threadIdx.x, lane = tid & 31, wid = tid >> 5;
    const int warp_m = wid >> 2, warp_n = wid & 3;
    const int z = blockIdx.z, zh = z >> hsh, zl = z & hmk;
    const int m0 = blockIdx.y << 7, n0 = blockIdx.x * NTILE;
    const float* Az = A + (size_t)zh * saz + (size_t)zl * sah + (size_t)m0 * lda;
    const float* Wz = W + (size_t)zh * swz + (size_t)zl * swh;
    const uint32_t sbase = smem_u32(smem);

    float acc[4 * NT * 4];
    #pragma unroll
    for (int i = 0; i < 4 * NT * 4; i++) acc[i] = 0.0f;

    float4 ra[4], rw[NTILE / 32];
    load_regs<NTILE, WTRANS>(Az, lda, Wz, ldw, n0, 0, tid, ra, rw);
    store_regs<NTILE, WTRANS>(smem, tid, ra, rw);
    __syncthreads();

    const int nchunk = K >> 5;
    for (int c = 0; c < nchunk; c++) {
        if (c + 1 < nchunk)
            load_regs<NTILE, WTRANS>(Az, lda, Wz, ldw, n0, c + 1, tid, ra, rw);
        compute_chunk<NT>(sbase + (c & 1) * STG, warp_m, warp_n, lane, acc);
        if (c + 1 < nchunk) {
            store_regs<NTILE, WTRANS>(smem + ((c + 1) & 1) * STG, tid, ra, rw);
            __syncthreads();
        }
    }

    // epilogue: each lane owns rows (lane>>2)+{0,8} per m-tile, cols 2*(lane&3)+{0,1}
    float* Cz = C + (size_t)zh * scz + (size_t)zl * sch;
    #pragma unroll
    for (int mt = 0; mt < 4; mt++) {
        #pragma unroll
        for (int h2 = 0; h2 < 2; h2++) {
            const int m = m0 + warp_m * 64 + mt * 16 + (lane >> 2) + h2 * 8;
            if (EPI == 4) { if (depths[m] < level) continue; }
            float* Crow = Cz + (size_t)m * ldc;
            const float* Rrow = (EPI >= 3) ? (res + (size_t)m * ldc) : (const float*)0;
            #pragma unroll
            for (int nt = 0; nt < NT; nt++) {
                const int col = n0 + warp_n * (NT * 8) + nt * 8 + ((lane & 3) << 1);
                float vx = acc[(mt * NT + nt) * 4 + h2 * 2 + 0];
                float vy = acc[(mt * NT + nt) * 4 + h2 * 2 + 1];
                if (EPI >= 1) { vx += bias[col]; vy += bias[col + 1]; }
                if (EPI == 2) { vx = gelu_erf(vx); vy = gelu_erf(vy); }
                if (EPI >= 3) { vx += Rrow[col]; vy += Rrow[col + 1]; }
                float2 o = make_float2(vx, vy);
                *(float2*)(Crow + col) = o;
            }
        }
    }
}

// ---------------- softmax (scale 1/8 fused) ----------------
__global__ void softmax_kernel(float* __restrict__ scores)
{
    size_t row = blockIdx.x;
    float4* p = (float4*)(scores + row * LL);
    float4 v = p[threadIdx.x];
    v.x *= 0.125f; v.y *= 0.125f; v.z *= 0.125f; v.w *= 0.125f;
    __shared__ float sh[8];
    float mx = warp_max(fmaxf(fmaxf(v.x, v.y), fmaxf(v.z, v.w)));
    int wid = threadIdx.x >> 5, lane = threadIdx.x & 31;
    if (lane == 0) sh[wid] = mx;
    __syncthreads();
    if (wid == 0) { float m = (lane < 8) ? sh[lane] : -1e30f; m = warp_max(m); if (lane == 0) sh[0] = m; }
    __syncthreads();
    float m = sh[0];
    __syncthreads();
    v.x = __expf(v.x - m); v.y = __expf(v.y - m); v.z = __expf(v.z - m); v.w = __expf(v.w - m);
    float s = warp_sum(v.x + v.y + v.z + v.w);
    if (lane == 0) sh[wid] = s;
    __syncthreads();
    if (wid == 0) { float t = (lane < 8) ? sh[lane] : 0.f; t = warp_sum(t); if (lane == 0) sh[0] = t; }
    __syncthreads();
    float inv = 1.0f / sh[0];
    v.x *= inv; v.y *= inv; v.z *= inv; v.w *= inv;
    p[threadIdx.x] = v;
}

// ---------------- LayerNorm ----------------
__global__ void ln_kernel(const float* __restrict__ in, const float* __restrict__ w,
                          const float* __restrict__ b, float* __restrict__ out)
{
    const int row = blockIdx.x;
    float4 v = ((const float4*)(in + (size_t)row * DD))[threadIdx.x];
    float s = warp_sum(v.x + v.y + v.z + v.w);
    float s2 = warp_sum(v.x * v.x + v.y * v.y + v.z * v.z + v.w * v.w);
    __shared__ float shs[8], shq[8];
    int wid = threadIdx.x >> 5, lane = threadIdx.x & 31;
    if (lane == 0) { shs[wid] = s; shq[wid] = s2; }
    __syncthreads();
    if (wid == 0) {
        float a = (lane < 8) ? shs[lane] : 0.f, c = (lane < 8) ? shq[lane] : 0.f;
        a = warp_sum(a); c = warp_sum(c);
        if (lane == 0) {
            float mu = a * (1.0f / DD);
            shs[0] = mu; shq[0] = rsqrtf(c * (1.0f / DD) - mu * mu + 1e-5f);
        }
    }
    __syncthreads();
    float mu = shs[0], rstd = shq[0];
    float4 wv = ((const float4*)w)[threadIdx.x], bv = ((const float4*)b)[threadIdx.x];
    float4 o;
    o.x = (v.x - mu) * rstd * wv.x + bv.x; o.y = (v.y - mu) * rstd * wv.y + bv.y;
    o.z = (v.z - mu) * rstd * wv.z + bv.z; o.w = (v.w - mu) * rstd * wv.w + bv.w;
    ((float4*)(out + (size_t)row * DD))[threadIdx.x] = o;
}

// ---------------- router ----------------
__global__ void router_kernel(const float* __restrict__ rh, const float* __restrict__ w2,
                              const float* __restrict__ b2, float* __restrict__ logits,
                              int* __restrict__ depths)
{
    const int row = blockIdx.x, tid = threadIdx.x;
    float part[MDD] = {0, 0, 0, 0, 0, 0};
    const float* x = rh + (size_t)row * DD;
    for (int i = tid; i < DD; i += 128) {
        float v = x[i];
        #pragma unroll
        for (int d = 0; d < MDD; d++) part[d] = fmaf(v, w2[d * DD + i], part[d]);
    }
    #pragma unroll
    for (int d = 0; d < MDD; d++) part[d] = warp_sum(part[d]);
    __shared__ float sh[MDD][4];
    int wid = tid >> 5, lane = tid & 31;
    if (lane == 0) {
        #pragma unroll
        for (int d = 0; d < MDD; d++) sh[d][wid] = part[d];
    }
    __syncthreads();
    if (tid == 0) {
        float best = -1e30f; int bi = 0;
        #pragma unroll
        for (int d = 0; d < MDD; d++) {
            float Lg = sh[d][0] + sh[d][1] + sh[d][2] + sh[d][3] + b2[d];
            logits[(size_t)row * MDD + d] = Lg;
            if (Lg > best) { best = Lg; bi = d; }
        }
        depths[row] = bi + 1;
    }
}

__global__ void copy_kernel(const float* __restrict__ in, float* __restrict__ out)
{
    size_t i = (size_t)blockIdx.x * blockDim.x + threadIdx.x;
    ((float4*)out)[i] = ((const float4*)in)[i];
}
__global__ void pack_kernel(const float* __restrict__ cur, const int* __restrict__ depths,
                            const float* __restrict__ logits, float* __restrict__ out, int out_size)
{
    int i = blockIdx.x * blockDim.x + threadIdx.x;
    if (i >= out_size) return;
    if (i < NCUR) out[i] = cur[i];
    else {
        int r = i - NCUR;
        if (r < ROWS) out[i] = (float)depths[r];
        else if (r - ROWS < ROWS * MDD) out[i] = logits[r - ROWS];
        else out[i] = 0.0f;
    }
}

// ---------------------------------------------------------------------------
#define SMEM128 (2 * (20480 + 2 * 128 * 80))   // 81920
#define SMEM64  (2 * (20480 + 2 * 64 * 80))    // 61440

extern "C" void kernel_launch(void* const* d_in, const int* in_sizes, int n_in,
                              void* d_out, int out_size)
{
    (void)in_sizes; (void)n_in;
    const float* x           = (const float*)d_in[0];
    const float* attn_norm_w = (const float*)d_in[1];
    const float* attn_norm_b = (const float*)d_in[2];
    const float* in_proj_w   = (const float*)d_in[3];
    const float* in_proj_b   = (const float*)d_in[4];
    const float* out_proj_w  = (const float*)d_in[5];
    const float* out_proj_b  = (const float*)d_in[6];
    const float* ffn_norm_w  = (const float*)d_in[7];
    const float* ffn_norm_b  = (const float*)d_in[8];
    const float* ffn_w1      = (const float*)d_in[9];
    const float* ffn_b1      = (const float*)d_in[10];
    const float* ffn_w2      = (const float*)d_in[11];
    const float* ffn_b2      = (const float*)d_in[12];
    const float* rt_norm_w   = (const float*)d_in[13];
    const float* rt_norm_b   = (const float*)d_in[14];
    const float* rt_w1       = (const float*)d_in[15];
    const float* rt_b1       = (const float*)d_in[16];
    const float* rt_w2       = (const float*)d_in[17];
    const float* rt_b2       = (const float*)d_in[18];

    float *cur, *ln, *qkv, *scores, *ctx, *x2, *hid, *logits;
    int* depths;
    cudaGetSymbolAddress((void**)&cur, g_cur);
    cudaGetSymbolAddress((void**)&ln, g_ln);
    cudaGetSymbolAddress((void**)&qkv, g_qkv);
    cudaGetSymbolAddress((void**)&scores, g_scores);
    cudaGetSymbolAddress((void**)&ctx, g_ctx);
    cudaGetSymbolAddress((void**)&x2, g_x2);
    cudaGetSymbolAddress((void**)&hid, g_hid);
    cudaGetSymbolAddress((void**)&logits, g_logits);
    cudaGetSymbolAddress((void**)&depths, g_depths);

    cudaFuncSetAttribute(gemm_mma<0,128,0>, cudaFuncAttributeMaxDynamicSharedMemorySize, SMEM128);
    cudaFuncSetAttribute(gemm_mma<0,64,1>,  cudaFuncAttributeMaxDynamicSharedMemorySize, SMEM64);
    cudaFuncSetAttribute(gemm_mma<1,128,0>, cudaFuncAttributeMaxDynamicSharedMemorySize, SMEM128);
    cudaFuncSetAttribute(gemm_mma<2,128,0>, cudaFuncAttributeMaxDynamicSharedMemorySize, SMEM128);
    cudaFuncSetAttribute(gemm_mma<3,128,0>, cudaFuncAttributeMaxDynamicSharedMemorySize, SMEM128);
    cudaFuncSetAttribute(gemm_mma<4,128,0>, cudaFuncAttributeMaxDynamicSharedMemorySize, SMEM128);

    copy_kernel<<<NCUR / 1024, 256>>>(x, cur);

    // ---- router ----
    ln_kernel<<<ROWS, 256>>>(x, rt_norm_w, rt_norm_b, ln);
    gemm_mma<2,128,0><<<dim3(8, 64, 1), 256, SMEM128>>>(
        ln, DD, 0, 0, rt_w1, DD, 0, 0, rt_b1, nullptr, nullptr, 0,
        ctx, DD, 0, 0, 0, 0, DD);
    router_kernel<<<ROWS, 128>>>(ctx, rt_w2, rt_b2, logits, depths);

    const long LQ = (long)LL * 3 * DD;
    const long SS = (long)LL * LL;

    for (int level = 1; level <= MDD; level++) {
        ln_kernel<<<ROWS, 256>>>(cur, attn_norm_w, attn_norm_b, ln);
        gemm_mma<1,128,0><<<dim3(24, 64, 1), 256, SMEM128>>>(
            ln, DD, 0, 0, in_proj_w, DD, 0, 0, in_proj_b, nullptr, nullptr, 0,
            qkv, 3 * DD, 0, 0, 0, 0, DD);
        // scores[z] = Q[z] @ K[z]^T,  z = b*16+h
        gemm_mma<0,128,0><<<dim3(8, 8, 128), 256, SMEM128>>>(
            qkv, 3 * DD, LQ, 64, qkv + DD, 3 * DD, LQ, 64, nullptr, nullptr, nullptr, 0,
            scores, LL, 16 * SS, SS, 4, 15, 64);
        softmax_kernel<<<128 * LL, 256>>>(scores);
        // ctx[z] = P[z] @ V[z]  (V transpose-on-load)
        gemm_mma<0,64,1><<<dim3(1, 8, 128), 256, SMEM64>>>(
            scores, LL, 16 * SS, SS, qkv + 2 * DD, 3 * DD, LQ, 64, nullptr, nullptr, nullptr, 0,
            ctx, DD, (long)LL * DD, 64, 4, 15, LL);
        gemm_mma<3,128,0><<<dim3(8, 64, 1), 256, SMEM128>>>(
            ctx, DD, 0, 0, out_proj_w, DD, 0, 0, out_proj_b, cur, nullptr, 0,
            x2, DD, 0, 0, 0, 0, DD);
        ln_kernel<<<ROWS, 256>>>(x2, ffn_norm_w, ffn_norm_b, ln);
        gemm_mma<2,128,0><<<dim3(32, 64, 1), 256, SMEM128>>>(
            ln, DD, 0, 0, ffn_w1, DD, 0, 0, ffn_b1, nullptr, nullptr, 0,
            hid, DFF, 0, 0, 0, 0, DD);
        gemm_mma<4,128,0><<<dim3(8, 64, 1), 256, SMEM128>>>(
            hid, DFF, 0, 0, ffn_w2, DFF, 0, 0, ffn_b2, x2, depths, level,
            cur, DD, 0, 0, 0, 0, DFF);
    }

    pack_kernel<<<(out_size + 255) / 256, 256>>>(cur, depths, logits, (float*)d_out, out_size);
}